// round 2
// baseline (speedup 1.0000x reference)
#include <cuda_runtime.h>

// Problem constants
#define BB 2
#define LL 64
#define DD 1024
#define HH 512
#define SS 50000
#define VV 40000
#define KK 32
#define MM 128   // B*L rows

// Scratch (device globals: allocation-free rule)
__device__ float g_scale[LL];
__device__ float g_shift[LL];
__device__ float g_ht[HH * MM];       // h transposed [H][M], 256 KB
__device__ float g_vt[VV * MM];       // v transposed [V][M], 20.5 MB (L2-resident)

// ---------------------------------------------------------------------------
// Kernel 1: BatchNorm stats per l-channel (stats over B*D = 2048 elems)
// ---------------------------------------------------------------------------
__global__ void bn_stats_kernel(const float* __restrict__ x,
                                const float* __restrict__ gamma,
                                const float* __restrict__ beta) {
    int l = blockIdx.x;
    int t = threadIdx.x;
    float s = 0.f, s2 = 0.f;
    for (int i = t; i < BB * DD; i += 256) {
        int b = i >> 10;
        int d = i & (DD - 1);
        float v = x[(b * LL + l) * DD + d];
        s += v;
        s2 += v * v;
    }
    __shared__ float rs[256], rs2[256];
    rs[t] = s; rs2[t] = s2;
    __syncthreads();
    for (int o = 128; o > 0; o >>= 1) {
        if (t < o) { rs[t] += rs[t + o]; rs2[t] += rs2[t + o]; }
        __syncthreads();
    }
    if (t == 0) {
        const float inv_n = 1.f / (BB * DD);
        float mean = rs[0] * inv_n;
        float var  = rs2[0] * inv_n - mean * mean;
        float rstd = rsqrtf(var + 1e-5f);
        float sc = gamma[l] * rstd;
        g_scale[l] = sc;
        g_shift[l] = beta[l] - mean * sc;
    }
}

// ---------------------------------------------------------------------------
// Kernel 2: h = relu(xn @ W1 + b1), stored transposed g_ht[j][bl]
// grid 16 blocks x 512 threads; each block does 8 bl rows, thread j = column
// ---------------------------------------------------------------------------
__global__ __launch_bounds__(512) void h_kernel(const float* __restrict__ x,
                                                const float* __restrict__ W1,
                                                const float* __restrict__ b1) {
    __shared__ float xs[8][DD];     // 32 KB
    int t = threadIdx.x;            // 0..511 == hidden index j
    int bl0 = blockIdx.x * 8;
    for (int i = t; i < 8 * DD; i += 512) {
        int r = i >> 10;
        int d = i & (DD - 1);
        int bl = bl0 + r;
        int l = bl & (LL - 1);
        xs[r][d] = x[bl * DD + d] * g_scale[l] + g_shift[l];
    }
    __syncthreads();
    float acc[8] = {0, 0, 0, 0, 0, 0, 0, 0};
#pragma unroll 4
    for (int d = 0; d < DD; ++d) {
        float w = W1[d * HH + t];
#pragma unroll
        for (int r = 0; r < 8; ++r) acc[r] += xs[r][d] * w;
    }
    float bj = b1[t];
#pragma unroll
    for (int r = 0; r < 8; ++r)
        g_ht[t * MM + bl0 + r] = fmaxf(acc[r] + bj, 0.f);
}

// ---------------------------------------------------------------------------
// Kernel 3: v^T = (h @ W_slm + b_slm)^T  -> g_vt[n][m], tiled 128x128, BK=32
// 256 threads, each an 8x8 microtile: m = ty*8+i (contiguous), n = tx+16*j
// ---------------------------------------------------------------------------
__global__ __launch_bounds__(256, 2) void vt_kernel(const float* __restrict__ Wslm,
                                                    const float* __restrict__ bslm) {
    __shared__ float As[32][MM];    // A^T tile: As[k][m]
    __shared__ float Bs[32][MM];    // B tile:   Bs[k][n]
    int t = threadIdx.x;
    int lane = t & 31, warp = t >> 5;
    int tx = t & 15, ty = t >> 4;
    int n0 = blockIdx.x * 128;

    float acc[8][8];
#pragma unroll
    for (int i = 0; i < 8; ++i)
#pragma unroll
        for (int j = 0; j < 8; ++j) acc[i][j] = 0.f;

    for (int kt = 0; kt < HH / 32; ++kt) {
        int k0 = kt * 32;
#pragma unroll
        for (int it = 0; it < 4; ++it) {
            int k = it * 8 + warp;
            *(float4*)&As[k][lane * 4] =
                *(const float4*)&g_ht[(k0 + k) * MM + lane * 4];
            int n4 = lane * 4;
            float4 bv = make_float4(0.f, 0.f, 0.f, 0.f);
            if (n0 + n4 < VV)
                bv = *(const float4*)&Wslm[(size_t)(k0 + k) * VV + n0 + n4];
            *(float4*)&Bs[k][n4] = bv;
        }
        __syncthreads();
#pragma unroll
        for (int k = 0; k < 32; ++k) {
            float4 a0 = *(const float4*)&As[k][ty * 8];
            float4 a1 = *(const float4*)&As[k][ty * 8 + 4];
            float a[8] = {a0.x, a0.y, a0.z, a0.w, a1.x, a1.y, a1.z, a1.w};
            float b[8];
#pragma unroll
            for (int j = 0; j < 8; ++j) b[j] = Bs[k][tx + 16 * j];
#pragma unroll
            for (int i = 0; i < 8; ++i)
#pragma unroll
                for (int j = 0; j < 8; ++j) acc[i][j] += a[i] * b[j];
        }
        __syncthreads();
    }
#pragma unroll
    for (int j = 0; j < 8; ++j) {
        int n = n0 + tx + 16 * j;
        if (n < VV) {
            float bn = __ldg(&bslm[n]);
            float4 v0 = make_float4(acc[0][j] + bn, acc[1][j] + bn,
                                    acc[2][j] + bn, acc[3][j] + bn);
            float4 v1 = make_float4(acc[4][j] + bn, acc[5][j] + bn,
                                    acc[6][j] + bn, acc[7][j] + bn);
            *(float4*)&g_vt[(size_t)n * MM + ty * 8]     = v0;
            *(float4*)&g_vt[(size_t)n * MM + ty * 8 + 4] = v1;
        }
    }
}

// ---------------------------------------------------------------------------
// Kernel 4: out = h@W2 + b2 + 0.1 * gather(v_t, sl_idx, sl_weights)
// Same GEMM shape; gather fused in epilogue, reusing smem (union) for idx/w.
// ---------------------------------------------------------------------------
struct GemmSmem   { float As[32][MM]; float Bs[32][MM]; };          // 32 KB
struct GatherSmem { int idx[128][KK]; float w[128][KK]; };          // 32 KB

__global__ __launch_bounds__(256, 2) void out_kernel(const float* __restrict__ W2,
                                                     const float* __restrict__ b2,
                                                     const float* __restrict__ slw,
                                                     const int*   __restrict__ slidx,
                                                     float* __restrict__ out) {
    __shared__ __align__(16) char smraw[sizeof(GemmSmem)];
    GemmSmem*   gs = (GemmSmem*)smraw;
    GatherSmem* hs = (GatherSmem*)smraw;

    int t = threadIdx.x;
    int lane = t & 31, warp = t >> 5;
    int tx = t & 15, ty = t >> 4;
    int n0 = blockIdx.x * 128;

    float acc[8][8];
#pragma unroll
    for (int i = 0; i < 8; ++i)
#pragma unroll
        for (int j = 0; j < 8; ++j) acc[i][j] = 0.f;

    for (int kt = 0; kt < HH / 32; ++kt) {
        int k0 = kt * 32;
#pragma unroll
        for (int it = 0; it < 4; ++it) {
            int k = it * 8 + warp;
            *(float4*)&gs->As[k][lane * 4] =
                *(const float4*)&g_ht[(k0 + k) * MM + lane * 4];
            int n4 = lane * 4;
            float4 bv = make_float4(0.f, 0.f, 0.f, 0.f);
            if (n0 + n4 < SS)
                bv = *(const float4*)&W2[(size_t)(k0 + k) * SS + n0 + n4];
            *(float4*)&gs->Bs[k][n4] = bv;
        }
        __syncthreads();
#pragma unroll
        for (int k = 0; k < 32; ++k) {
            float4 a0 = *(const float4*)&gs->As[k][ty * 8];
            float4 a1 = *(const float4*)&gs->As[k][ty * 8 + 4];
            float a[8] = {a0.x, a0.y, a0.z, a0.w, a1.x, a1.y, a1.z, a1.w};
            float b[8];
#pragma unroll
            for (int j = 0; j < 8; ++j) b[j] = gs->Bs[k][tx + 16 * j];
#pragma unroll
            for (int i = 0; i < 8; ++i)
#pragma unroll
                for (int j = 0; j < 8; ++j) acc[i][j] += a[i] * b[j];
        }
        __syncthreads();
    }

    // stage idx/weights (smem reuse; GEMM tiles dead after last barrier)
    for (int i = t; i < 128 * KK; i += 256) {
        int n = i >> 5;
        int k = i & (KK - 1);
        int gn = n0 + n;
        if (gn < SS) {
            hs->idx[n][k] = slidx[gn * KK + k];
            hs->w[n][k]   = slw[gn * KK + k];
        } else {
            hs->idx[n][k] = 0;
            hs->w[n][k]   = 0.f;
        }
    }
    __syncthreads();

#pragma unroll
    for (int j = 0; j < 8; ++j) {
        int n = tx + 16 * j;
        int gn = n0 + n;
        float sacc[8] = {0, 0, 0, 0, 0, 0, 0, 0};
#pragma unroll 4
        for (int k = 0; k < KK; ++k) {
            int row = hs->idx[n][k];
            float wk = hs->w[n][k];
            const float4* p = (const float4*)&g_vt[(size_t)row * MM + ty * 8];
            float4 va = p[0];
            float4 vb = p[1];
            sacc[0] += va.x * wk; sacc[1] += va.y * wk;
            sacc[2] += va.z * wk; sacc[3] += va.w * wk;
            sacc[4] += vb.x * wk; sacc[5] += vb.y * wk;
            sacc[6] += vb.z * wk; sacc[7] += vb.w * wk;
        }
        if (gn < SS) {
            float bb = __ldg(&b2[gn]);
#pragma unroll
            for (int i = 0; i < 8; ++i) {
                int m = ty * 8 + i;
                out[(size_t)m * SS + gn] = acc[i][j] + bb + 0.1f * sacc[i];
            }
        }
    }
}

// ---------------------------------------------------------------------------
// Launch
// ---------------------------------------------------------------------------
extern "C" void kernel_launch(void* const* d_in, const int* in_sizes, int n_in,
                              void* d_out, int out_size) {
    const float* x     = (const float*)d_in[0];   // [B,L,D]
    const float* gamma = (const float*)d_in[1];   // [L]
    const float* beta  = (const float*)d_in[2];   // [L]
    const float* W1    = (const float*)d_in[3];   // [D,H]
    const float* b1    = (const float*)d_in[4];   // [H]
    const float* W2    = (const float*)d_in[5];   // [H,S]
    const float* b2    = (const float*)d_in[6];   // [S]
    const float* Wslm  = (const float*)d_in[7];   // [H,V]
    const float* bslm  = (const float*)d_in[8];   // [V]
    const float* slw   = (const float*)d_in[9];   // [S,K]
    const int*   slidx = (const int*)d_in[10];    // [S,K]
    float* out = (float*)d_out;                   // [B,L,S]

    bn_stats_kernel<<<LL, 256>>>(x, gamma, beta);
    h_kernel<<<MM / 8, 512>>>(x, W1, b1);
    vt_kernel<<<(VV + 127) / 128, 256>>>(Wslm, bslm);
    out_kernel<<<(SS + 127) / 128, 256>>>(W2, b2, slw, slidx, out);
}

// round 4
// speedup vs baseline: 2.4693x; 2.4693x over previous
#include <cuda_runtime.h>
#include <cuda_bf16.h>

#define BB 2
#define LL 64
#define DD 1024
#define HH 512
#define SSN 50000
#define VVN 40000
#define KK 32
#define MM 128
#define BKC 32

// ---------------- device scratch ----------------
__device__ float g_scale[LL];
__device__ float g_shift[LL];
__device__ __align__(16) __nv_bfloat16 g_hhi[MM * HH];          // h hi [m][k]
__device__ __align__(16) __nv_bfloat16 g_hlo[MM * HH];          // h lo [m][k]
__device__ __align__(16) __nv_bfloat16 g_vt[(size_t)VVN * MM];  // v^T bf16 [V][128]

// ---------------- smem layout (bytes) ----------------
#define A_HI_OFF 0          // [128][32] bf16, 64B rows, XOR swizzle   (8192)
#define A_LO_OFF 8192
#define B_HI_OFF 16384      // [32][136] bf16, 272B rows               (8704)
#define B_LO_OFF 25088
#define STAGE_SZ 33792      // x2 stages = 67584
#define YS_PITCH 133        // ys[128][133] f32 = 68096
#define IDX_OFF  68096
#define WTS_OFF  84480
#define SMEM_BYTES 100864

__device__ __forceinline__ unsigned smem_u32(const void* p) {
    unsigned a;
    asm("{ .reg .u64 t; cvta.to.shared.u64 t, %1; cvt.u32.u64 %0, t; }"
        : "=r"(a) : "l"(p));
    return a;
}
__device__ __forceinline__ void ldsm4(unsigned& r0, unsigned& r1, unsigned& r2,
                                      unsigned& r3, unsigned addr) {
    asm volatile("ldmatrix.sync.aligned.m8n8.x4.shared.b16 {%0,%1,%2,%3}, [%4];"
                 : "=r"(r0), "=r"(r1), "=r"(r2), "=r"(r3) : "r"(addr));
}
__device__ __forceinline__ void ldsm4t(unsigned& r0, unsigned& r1, unsigned& r2,
                                       unsigned& r3, unsigned addr) {
    asm volatile("ldmatrix.sync.aligned.m8n8.x4.trans.shared.b16 {%0,%1,%2,%3}, [%4];"
                 : "=r"(r0), "=r"(r1), "=r"(r2), "=r"(r3) : "r"(addr));
}
__device__ __forceinline__ void mma_bf16(float* d, const unsigned* a,
                                         unsigned b0, unsigned b1) {
    asm volatile(
        "mma.sync.aligned.m16n8k16.row.col.f32.bf16.bf16.f32 "
        "{%0,%1,%2,%3}, {%4,%5,%6,%7}, {%8,%9}, {%0,%1,%2,%3};"
        : "+f"(d[0]), "+f"(d[1]), "+f"(d[2]), "+f"(d[3])
        : "r"(a[0]), "r"(a[1]), "r"(a[2]), "r"(a[3]), "r"(b0), "r"(b1));
}
__device__ __forceinline__ void cvt_hilo(float4 v, uint2& hw, uint2& lw) {
    __nv_bfloat162 h0 = __floats2bfloat162_rn(v.x, v.y);
    __nv_bfloat162 h1 = __floats2bfloat162_rn(v.z, v.w);
    float2 f0 = __bfloat1622float2(h0), f1 = __bfloat1622float2(h1);
    __nv_bfloat162 l0 = __floats2bfloat162_rn(v.x - f0.x, v.y - f0.y);
    __nv_bfloat162 l1 = __floats2bfloat162_rn(v.z - f1.x, v.w - f1.y);
    hw.x = *(unsigned*)&h0; hw.y = *(unsigned*)&h1;
    lw.x = *(unsigned*)&l0; lw.y = *(unsigned*)&l1;
}

// ---------------------------------------------------------------------------
// Kernel 1: BN stats
// ---------------------------------------------------------------------------
__global__ void bn_stats_kernel(const float* __restrict__ x,
                                const float* __restrict__ gamma,
                                const float* __restrict__ beta) {
    int l = blockIdx.x, t = threadIdx.x;
    float s = 0.f, s2 = 0.f;
    for (int i = t; i < BB * DD; i += 256) {
        int b = i >> 10, d = i & (DD - 1);
        float v = x[(b * LL + l) * DD + d];
        s += v; s2 += v * v;
    }
    __shared__ float rs[256], rs2[256];
    rs[t] = s; rs2[t] = s2;
    __syncthreads();
    for (int o = 128; o > 0; o >>= 1) {
        if (t < o) { rs[t] += rs[t + o]; rs2[t] += rs2[t + o]; }
        __syncthreads();
    }
    if (t == 0) {
        const float inv_n = 1.f / (BB * DD);
        float mean = rs[0] * inv_n;
        float var  = rs2[0] * inv_n - mean * mean;
        float sc = gamma[l] * rsqrtf(var + 1e-5f);
        g_scale[l] = sc;
        g_shift[l] = beta[l] - mean * sc;
    }
}

// ---------------------------------------------------------------------------
// Kernel 2: h = relu(xn@W1+b1) -> bf16 hi/lo [m][k]
// ---------------------------------------------------------------------------
__global__ __launch_bounds__(512) void h_kernel(const float* __restrict__ x,
                                                const float* __restrict__ W1,
                                                const float* __restrict__ b1) {
    __shared__ float xs[8][DD];
    int t = threadIdx.x;
    int bl0 = blockIdx.x * 8;
    for (int i = t; i < 8 * DD; i += 512) {
        int r = i >> 10, d = i & (DD - 1);
        int bl = bl0 + r, l = bl & (LL - 1);
        xs[r][d] = x[bl * DD + d] * g_scale[l] + g_shift[l];
    }
    __syncthreads();
    float acc[8] = {0, 0, 0, 0, 0, 0, 0, 0};
#pragma unroll 4
    for (int d = 0; d < DD; ++d) {
        float w = W1[d * HH + t];
#pragma unroll
        for (int r = 0; r < 8; ++r) acc[r] += xs[r][d] * w;
    }
    float bj = b1[t];
#pragma unroll
    for (int r = 0; r < 8; ++r) {
        float v = fmaxf(acc[r] + bj, 0.f);
        __nv_bfloat16 hi = __float2bfloat16(v);
        g_hhi[(bl0 + r) * HH + t] = hi;
        g_hlo[(bl0 + r) * HH + t] = __float2bfloat16(v - __bfloat162float(hi));
    }
}

// ---------------------------------------------------------------------------
// HMMA GEMM: D[128 x 128-tile] = h[128x512] @ W[512xNN], bf16-split x3
// ---------------------------------------------------------------------------
template <int NN, bool GATHER>
__global__ __launch_bounds__(256) void gemm_kernel(const float* __restrict__ W,
                                                   const float* __restrict__ bias,
                                                   const float* __restrict__ slw,
                                                   const int*   __restrict__ slidx,
                                                   float* __restrict__ out) {
    extern __shared__ __align__(128) char smem[];
    const int t = threadIdx.x;
    const int lane = t & 31, w = t >> 5;
    const int wm = (w >> 2) * 64, wn = (w & 3) * 32;
    const int n0g = blockIdx.x * 128;
    const unsigned sb = smem_u32(smem);

    // staging indices
    const int am = t >> 1;              // A row (m)
    const int ach = (t & 1) * 2;        // A chunk pair (16B chunks)
    const int bk = t >> 3;              // B row (k)
    const int bn = (t & 7) * 16;        // B col base

    float acc[4][4][4];
#pragma unroll
    for (int i = 0; i < 4; ++i)
#pragma unroll
        for (int j = 0; j < 4; ++j)
#pragma unroll
            for (int e = 0; e < 4; ++e) acc[i][j][e] = 0.f;

    uint4 pAh0, pAh1, pAl0, pAl1;
    float4 pB[4];

    auto prefetch = [&](int c) {
        int k0 = c * BKC;
        const uint4* ph = (const uint4*)&g_hhi[am * HH + k0 + (t & 1) * 16];
        pAh0 = ph[0]; pAh1 = ph[1];
        const uint4* pl = (const uint4*)&g_hlo[am * HH + k0 + (t & 1) * 16];
        pAl0 = pl[0]; pAl1 = pl[1];
        const float* wr = W + (size_t)(k0 + bk) * NN + n0g + bn;
#pragma unroll
        for (int j = 0; j < 4; ++j) {
            int gn = n0g + bn + j * 4;
            pB[j] = (gn < NN) ? *(const float4*)(wr + j * 4)
                              : make_float4(0.f, 0.f, 0.f, 0.f);
        }
    };
    auto store_stage = [&](int c) {
        char* st = smem + (c & 1) * STAGE_SZ;
        int sw = (am >> 1) & 3;
        *(uint4*)(st + A_HI_OFF + am * 64 + ((ach)     ^ sw) * 16) = pAh0;
        *(uint4*)(st + A_HI_OFF + am * 64 + ((ach + 1) ^ sw) * 16) = pAh1;
        *(uint4*)(st + A_LO_OFF + am * 64 + ((ach)     ^ sw) * 16) = pAl0;
        *(uint4*)(st + A_LO_OFF + am * 64 + ((ach + 1) ^ sw) * 16) = pAl1;
#pragma unroll
        for (int j = 0; j < 4; ++j) {
            uint2 hw, lw;
            cvt_hilo(pB[j], hw, lw);
            *(uint2*)(st + B_HI_OFF + bk * 272 + (bn + j * 4) * 2) = hw;
            *(uint2*)(st + B_LO_OFF + bk * 272 + (bn + j * 4) * 2) = lw;
        }
    };

    prefetch(0);
    store_stage(0);
    __syncthreads();

    const unsigned bBase = (unsigned)((lane & 15) * 272 +
                                      (wn + (lane >> 4) * 8) * 2);

    for (int c = 0; c < HH / BKC; ++c) {
        if (c < HH / BKC - 1) prefetch(c + 1);
        const unsigned stgb = sb + (unsigned)(c & 1) * STAGE_SZ;
#pragma unroll
        for (int p = 0; p < 3; ++p) {
            const unsigned ao = (p == 2) ? A_LO_OFF : A_HI_OFF;
            const unsigned bo = (p == 1) ? B_LO_OFF : B_HI_OFF;
#pragma unroll
            for (int ks = 0; ks < 2; ++ks) {
                unsigned a[4][4], bf[2][4];
#pragma unroll
                for (int mi = 0; mi < 4; ++mi) {
                    int row = wm + mi * 16 + (lane & 15);
                    int chunk = (ks * 2 + (lane >> 4)) ^ ((row >> 1) & 3);
                    ldsm4(a[mi][0], a[mi][1], a[mi][2], a[mi][3],
                          stgb + ao + row * 64 + chunk * 16);
                }
#pragma unroll
                for (int g = 0; g < 2; ++g)
                    ldsm4t(bf[g][0], bf[g][1], bf[g][2], bf[g][3],
                           stgb + bo + bBase + ks * 4352 + g * 32);
#pragma unroll
                for (int mi = 0; mi < 4; ++mi)
#pragma unroll
                    for (int nj = 0; nj < 4; ++nj)
                        mma_bf16(acc[mi][nj], a[mi],
                                 bf[nj >> 1][(nj & 1) * 2],
                                 bf[nj >> 1][(nj & 1) * 2 + 1]);
            }
        }
        if (c < HH / BKC - 1) {
            store_stage(c + 1);
            __syncthreads();
        }
    }
    __syncthreads();

    // ---- epilogue: acc -> ys[128][133] ----
    float* ys = (float*)smem;
#pragma unroll
    for (int mi = 0; mi < 4; ++mi)
#pragma unroll
        for (int nj = 0; nj < 4; ++nj) {
            int row = wm + mi * 16 + (lane >> 2);
            int col = wn + nj * 8 + (lane & 3) * 2;
            float* d = acc[mi][nj];
            ys[row * YS_PITCH + col]           = d[0];
            ys[row * YS_PITCH + col + 1]       = d[1];
            ys[(row + 8) * YS_PITCH + col]     = d[2];
            ys[(row + 8) * YS_PITCH + col + 1] = d[3];
        }
    int* idx_s = (int*)(smem + IDX_OFF);
    float* w_s = (float*)(smem + WTS_OFF);
    if (GATHER) {
        for (int i = t; i < 128 * KK; i += 256) {
            int gn = n0g + (i >> 5);
            idx_s[i] = (gn < NN) ? slidx[gn * KK + (i & 31)] : 0;
            w_s[i]   = (gn < NN) ? slw[gn * KK + (i & 31)] : 0.f;
        }
    }
    __syncthreads();

    const int m = (w & 3) * 32 + lane;
    if (GATHER) {
#pragma unroll
        for (int ch = 0; ch < 2; ++ch) {
            int col0 = (w >> 2) * 64 + ch * 32;
#pragma unroll 1
            for (int n = 0; n < 32; ++n) {
                int col = col0 + n;
                int gn = n0g + col;
                const int*   ip = &idx_s[col * KK];
                const float* wp = &w_s[col * KK];
                float s0 = 0.f, s1 = 0.f, s2 = 0.f, s3 = 0.f;
#pragma unroll
                for (int k = 0; k < KK; k += 4) {
                    s0 += wp[k]     * __bfloat162float(g_vt[(size_t)ip[k]     * MM + m]);
                    s1 += wp[k + 1] * __bfloat162float(g_vt[(size_t)ip[k + 1] * MM + m]);
                    s2 += wp[k + 2] * __bfloat162float(g_vt[(size_t)ip[k + 2] * MM + m]);
                    s3 += wp[k + 3] * __bfloat162float(g_vt[(size_t)ip[k + 3] * MM + m]);
                }
                float bv = (gn < NN) ? __ldg(&bias[gn]) : 0.f;
                ys[m * YS_PITCH + col] += bv + 0.1f * ((s0 + s1) + (s2 + s3));
            }
        }
        __syncthreads();
        for (int i = t; i < 128 * 128; i += 256) {
            int row = i >> 7, col = i & 127;
            int gn = n0g + col;
            if (gn < NN) out[(size_t)row * NN + gn] = ys[row * YS_PITCH + col];
        }
    } else {
#pragma unroll
        for (int ch = 0; ch < 2; ++ch) {
            int col0 = (w >> 2) * 64 + ch * 32;
#pragma unroll 1
            for (int n = 0; n < 32; ++n) {
                int col = col0 + n;
                int gn = n0g + col;
                if (gn < NN)
                    g_vt[(size_t)gn * MM + m] =
                        __float2bfloat16(ys[m * YS_PITCH + col] + __ldg(&bias[gn]));
            }
        }
    }
}

// ---------------------------------------------------------------------------
extern "C" void kernel_launch(void* const* d_in, const int* in_sizes, int n_in,
                              void* d_out, int out_size) {
    const float* x     = (const float*)d_in[0];
    const float* gamma = (const float*)d_in[1];
    const float* beta  = (const float*)d_in[2];
    const float* W1    = (const float*)d_in[3];
    const float* b1    = (const float*)d_in[4];
    const float* W2    = (const float*)d_in[5];
    const float* b2    = (const float*)d_in[6];
    const float* Wslm  = (const float*)d_in[7];
    const float* bslm  = (const float*)d_in[8];
    const float* slw   = (const float*)d_in[9];
    const int*   slidx = (const int*)d_in[10];
    float* out = (float*)d_out;

    static bool attr_done = false;
    if (!attr_done) {
        cudaFuncSetAttribute(gemm_kernel<VVN, false>,
                             cudaFuncAttributeMaxDynamicSharedMemorySize, SMEM_BYTES);
        cudaFuncSetAttribute(gemm_kernel<SSN, true>,
                             cudaFuncAttributeMaxDynamicSharedMemorySize, SMEM_BYTES);
        attr_done = true;
    }

    bn_stats_kernel<<<LL, 256>>>(x, gamma, beta);
    h_kernel<<<MM / 8, 512>>>(x, W1, b1);
    gemm_kernel<VVN, false><<<(VVN + 127) / 128, 256, SMEM_BYTES>>>(
        Wslm, bslm, nullptr, nullptr, nullptr);
    gemm_kernel<SSN, true><<<(SSN + 127) / 128, 256, SMEM_BYTES>>>(
        W2, b2, slw, slidx, out);
}

// round 5
// speedup vs baseline: 3.6788x; 1.4899x over previous
#include <cuda_runtime.h>
#include <cuda_bf16.h>

#define BB 2
#define LL 64
#define DD 1024
#define HH 512
#define SSN 50000
#define VVN 40000
#define KK 32
#define MM 128
#define BKC 32

// ---------------- device scratch ----------------
__device__ float g_scale[LL];
__device__ float g_shift[LL];
__device__ __align__(16) __nv_bfloat16 g_hhi[MM * HH];          // h hi [m][k]
__device__ __align__(16) __nv_bfloat16 g_hlo[MM * HH];          // h lo [m][k]
__device__ __align__(16) __nv_bfloat16 g_vt[(size_t)VVN * MM];  // v^T bf16 [V][128]

// ---------------- smem layout (bytes) ----------------
#define A_HI_OFF 0          // [128][32] bf16, 64B rows, XOR swizzle (8192)
#define A_LO_OFF 8192
#define B_HI_OFF 16384      // [32][136] bf16, 272B rows (8704)
#define B_LO_OFF 25088
#define STAGE_SZ 33792      // x2 stages = 67584
#define YS_PITCH 66         // ys[128][66] f32 = 33792 (overlays stage 0)
#define IDX_OFF  33792      // idx_s[64][32] int (8192)
#define WTS_OFF  41984      // w_s[64][32] f32 (8192)
#define BIA_OFF  50176      // b_s[64] f32 (256)
#define SMEM_BYTES 67584

__device__ __forceinline__ unsigned smem_u32(const void* p) {
    unsigned a;
    asm("{ .reg .u64 t; cvta.to.shared.u64 t, %1; cvt.u32.u64 %0, t; }"
        : "=r"(a) : "l"(p));
    return a;
}
#define CP_ASYNC16(dst, src) \
    asm volatile("cp.async.cg.shared.global [%0], [%1], 16;" :: "r"(dst), "l"(src))
#define CP_COMMIT() asm volatile("cp.async.commit_group;" ::: "memory")
#define CP_WAIT0()  asm volatile("cp.async.wait_group 0;" ::: "memory")

__device__ __forceinline__ void ldsm4(unsigned& r0, unsigned& r1, unsigned& r2,
                                      unsigned& r3, unsigned addr) {
    asm volatile("ldmatrix.sync.aligned.m8n8.x4.shared.b16 {%0,%1,%2,%3}, [%4];"
                 : "=r"(r0), "=r"(r1), "=r"(r2), "=r"(r3) : "r"(addr));
}
__device__ __forceinline__ void ldsm4t(unsigned& r0, unsigned& r1, unsigned& r2,
                                       unsigned& r3, unsigned addr) {
    asm volatile("ldmatrix.sync.aligned.m8n8.x4.trans.shared.b16 {%0,%1,%2,%3}, [%4];"
                 : "=r"(r0), "=r"(r1), "=r"(r2), "=r"(r3) : "r"(addr));
}
__device__ __forceinline__ void mma_bf16(float* d, const unsigned* a,
                                         unsigned b0, unsigned b1) {
    asm volatile(
        "mma.sync.aligned.m16n8k16.row.col.f32.bf16.bf16.f32 "
        "{%0,%1,%2,%3}, {%4,%5,%6,%7}, {%8,%9}, {%0,%1,%2,%3};"
        : "+f"(d[0]), "+f"(d[1]), "+f"(d[2]), "+f"(d[3])
        : "r"(a[0]), "r"(a[1]), "r"(a[2]), "r"(a[3]), "r"(b0), "r"(b1));
}
__device__ __forceinline__ void cvt_hilo(float4 v, uint2& hw, uint2& lw) {
    __nv_bfloat162 h0 = __floats2bfloat162_rn(v.x, v.y);
    __nv_bfloat162 h1 = __floats2bfloat162_rn(v.z, v.w);
    float2 f0 = __bfloat1622float2(h0), f1 = __bfloat1622float2(h1);
    __nv_bfloat162 l0 = __floats2bfloat162_rn(v.x - f0.x, v.y - f0.y);
    __nv_bfloat162 l1 = __floats2bfloat162_rn(v.z - f1.x, v.w - f1.y);
    hw.x = *(unsigned*)&h0; hw.y = *(unsigned*)&h1;
    lw.x = *(unsigned*)&l0; lw.y = *(unsigned*)&l1;
}

// ---------------------------------------------------------------------------
// Kernel 1: BN stats
// ---------------------------------------------------------------------------
__global__ void bn_stats_kernel(const float* __restrict__ x,
                                const float* __restrict__ gamma,
                                const float* __restrict__ beta) {
    int l = blockIdx.x, t = threadIdx.x;
    float s = 0.f, s2 = 0.f;
    for (int i = t; i < BB * DD; i += 256) {
        int b = i >> 10, d = i & (DD - 1);
        float v = x[(b * LL + l) * DD + d];
        s += v; s2 += v * v;
    }
    __shared__ float rs[256], rs2[256];
    rs[t] = s; rs2[t] = s2;
    __syncthreads();
    for (int o = 128; o > 0; o >>= 1) {
        if (t < o) { rs[t] += rs[t + o]; rs2[t] += rs2[t + o]; }
        __syncthreads();
    }
    if (t == 0) {
        const float inv_n = 1.f / (BB * DD);
        float mean = rs[0] * inv_n;
        float var  = rs2[0] * inv_n - mean * mean;
        float sc = gamma[l] * rsqrtf(var + 1e-5f);
        g_scale[l] = sc;
        g_shift[l] = beta[l] - mean * sc;
    }
}

// ---------------------------------------------------------------------------
// Kernel 2: h = relu(xn@W1+b1) -> bf16 hi/lo [m][k]; one bl-row per block
// ---------------------------------------------------------------------------
__global__ __launch_bounds__(512) void h_kernel(const float* __restrict__ x,
                                                const float* __restrict__ W1,
                                                const float* __restrict__ b1) {
    __shared__ float xs[DD];
    int t = threadIdx.x;
    int bl = blockIdx.x, l = bl & (LL - 1);
    for (int d = t; d < DD; d += 512)
        xs[d] = x[bl * DD + d] * g_scale[l] + g_shift[l];
    __syncthreads();
    float acc = 0.f;
#pragma unroll 16
    for (int d = 0; d < DD; ++d) acc += xs[d] * W1[d * HH + t];
    float v = fmaxf(acc + b1[t], 0.f);
    __nv_bfloat16 hi = __float2bfloat16(v);
    g_hhi[bl * HH + t] = hi;
    g_hlo[bl * HH + t] = __float2bfloat16(v - __bfloat162float(hi));
}

// ---------------------------------------------------------------------------
// HMMA GEMM: D[128 x 128-tile] = h[128x512] @ W[512xNN], bf16-split x3
// ---------------------------------------------------------------------------
template <int NN, bool GATHER>
__global__ __launch_bounds__(256, 2) void gemm_kernel(const float* __restrict__ W,
                                                      const float* __restrict__ bias,
                                                      const float* __restrict__ slw,
                                                      const int*   __restrict__ slidx,
                                                      float* __restrict__ out) {
    extern __shared__ __align__(128) char smem[];
    const int t = threadIdx.x;
    const int lane = t & 31, w = t >> 5;
    const int wm = (w >> 2) * 64, wn = (w & 3) * 32;
    const int n0g = blockIdx.x * 128;
    const unsigned sb = smem_u32(smem);

    const int bk = t >> 3;              // B row (k)
    const int bn = (t & 7) * 16;        // B col base

    float acc[4][4][4];
#pragma unroll
    for (int i = 0; i < 4; ++i)
#pragma unroll
        for (int j = 0; j < 4; ++j)
#pragma unroll
            for (int e = 0; e < 4; ++e) acc[i][j][e] = 0.f;

    uint2 pBh[4], pBl[4];

    auto copyA = [&](int c) {
        unsigned stg = sb + (unsigned)(c & 1) * STAGE_SZ;
        int k0 = c * BKC;
#pragma unroll
        for (int j = 0; j < 2; ++j) {
            int id = t + 256 * j;
            int m = id >> 2, ch = id & 3;
            unsigned off = (unsigned)(m * 64 + ((ch ^ ((m >> 1) & 3))) * 16);
            CP_ASYNC16(stg + A_HI_OFF + off, &g_hhi[m * HH + k0 + ch * 8]);
            CP_ASYNC16(stg + A_LO_OFF + off, &g_hlo[m * HH + k0 + ch * 8]);
        }
    };
    auto prefB = [&](int c) {
        int k0 = c * BKC;
        const float* wr = W + (size_t)(k0 + bk) * NN + n0g + bn;
#pragma unroll
        for (int j = 0; j < 4; ++j) {
            int gn = n0g + bn + j * 4;
            float4 v = (gn < NN) ? *(const float4*)(wr + j * 4)
                                 : make_float4(0.f, 0.f, 0.f, 0.f);
            cvt_hilo(v, pBh[j], pBl[j]);
        }
    };
    auto stsB = [&](int c) {
        char* st = smem + (c & 1) * STAGE_SZ;
#pragma unroll
        for (int j = 0; j < 4; ++j) {
            *(uint2*)(st + B_HI_OFF + bk * 272 + (bn + j * 4) * 2) = pBh[j];
            *(uint2*)(st + B_LO_OFF + bk * 272 + (bn + j * 4) * 2) = pBl[j];
        }
    };

    copyA(0); CP_COMMIT();
    prefB(0); stsB(0);
    CP_WAIT0();
    __syncthreads();

    const unsigned bBase = (unsigned)((lane & 15) * 272 +
                                      (wn + (lane >> 4) * 8) * 2);

    for (int c = 0; c < HH / BKC; ++c) {
        if (c < HH / BKC - 1) {
            prefB(c + 1);
            copyA(c + 1); CP_COMMIT();
        }
        const unsigned stgb = sb + (unsigned)(c & 1) * STAGE_SZ;
#pragma unroll
        for (int p = 0; p < 3; ++p) {
            const unsigned ao = (p == 2) ? A_LO_OFF : A_HI_OFF;
            const unsigned bo = (p == 1) ? B_LO_OFF : B_HI_OFF;
#pragma unroll
            for (int ks = 0; ks < 2; ++ks) {
                unsigned a[4][4], bf[2][4];
#pragma unroll
                for (int mi = 0; mi < 4; ++mi) {
                    int row = wm + mi * 16 + (lane & 15);
                    int chunk = (ks * 2 + (lane >> 4)) ^ ((row >> 1) & 3);
                    ldsm4(a[mi][0], a[mi][1], a[mi][2], a[mi][3],
                          stgb + ao + row * 64 + chunk * 16);
                }
#pragma unroll
                for (int g = 0; g < 2; ++g)
                    ldsm4t(bf[g][0], bf[g][1], bf[g][2], bf[g][3],
                           stgb + bo + bBase + ks * 4352 + g * 32);
#pragma unroll
                for (int mi = 0; mi < 4; ++mi)
#pragma unroll
                    for (int nj = 0; nj < 4; ++nj)
                        mma_bf16(acc[mi][nj], a[mi],
                                 bf[nj >> 1][(nj & 1) * 2],
                                 bf[nj >> 1][(nj & 1) * 2 + 1]);
            }
        }
        if (c < HH / BKC - 1) {
            stsB(c + 1);
            CP_WAIT0();
            __syncthreads();
        }
    }
    __syncthreads();

    // ---- epilogue: two half-passes over 64 columns each ----
    float* ys   = (float*)smem;
    int*   idx_s = (int*)(smem + IDX_OFF);
    float* w_s  = (float*)(smem + WTS_OFF);
    float* b_s  = (float*)(smem + BIA_OFF);

#pragma unroll 1
    for (int hf = 0; hf < 2; ++hf) {
        const int h0 = hf * 64;
        if (GATHER) {
            for (int i = t; i < 64 * KK; i += 256) {
                int gn = n0g + h0 + (i >> 5);
                idx_s[i] = (gn < NN) ? slidx[(size_t)gn * KK + (i & 31)] : 0;
                w_s[i]   = (gn < NN) ? slw[(size_t)gn * KK + (i & 31)] : 0.f;
            }
        }
        if (t < 64) {
            int gn = n0g + h0 + t;
            b_s[t] = (gn < NN) ? bias[gn] : 0.f;
        }
        // acc -> ys for warps whose columns lie in this half
        if (((w & 3) >> 1) == hf) {
            int wn2 = ((w & 3) & 1) * 32;
#pragma unroll
            for (int mi = 0; mi < 4; ++mi)
#pragma unroll
                for (int nj = 0; nj < 4; ++nj) {
                    int row = wm + mi * 16 + (lane >> 2);
                    int col = wn2 + nj * 8 + (lane & 3) * 2;
                    float* d = acc[mi][nj];
                    ys[row * YS_PITCH + col]           = d[0];
                    ys[row * YS_PITCH + col + 1]       = d[1];
                    ys[(row + 8) * YS_PITCH + col]     = d[2];
                    ys[(row + 8) * YS_PITCH + col + 1] = d[3];
                }
        }
        __syncthreads();

        if (GATHER) {
            const int m0 = (w >> 2) * 64 + 2 * lane;
#pragma unroll 1
            for (int i = 0; i < 16; ++i) {
                int cw = (w & 3) * 16 + i;
                const int*   ip = &idx_s[cw * KK];
                const float* wp = &w_s[cw * KK];
                float a0 = 0.f, a1 = 0.f;
#pragma unroll 8
                for (int k = 0; k < KK; ++k) {
                    float wk = wp[k];
                    __nv_bfloat162 v =
                        *(const __nv_bfloat162*)&g_vt[(size_t)ip[k] * MM + m0];
                    float2 f = __bfloat1622float2(v);
                    a0 += wk * f.x;
                    a1 += wk * f.y;
                }
                ys[m0 * YS_PITCH + cw]       += 0.1f * a0;
                ys[(m0 + 1) * YS_PITCH + cw] += 0.1f * a1;
            }
            __syncthreads();
            for (int i = t; i < 128 * 64; i += 256) {
                int row = i >> 6, col = i & 63;
                int gn = n0g + h0 + col;
                if (gn < NN)
                    out[(size_t)row * NN + gn] = ys[row * YS_PITCH + col] + b_s[col];
            }
        } else {
            for (int i = t; i < 64 * 64; i += 256) {
                int r2 = i & 63, col = i >> 6;
                int gn = n0g + h0 + col;
                if (gn < NN) {
                    float bv = b_s[col];
                    __nv_bfloat162 pv = __floats2bfloat162_rn(
                        ys[(2 * r2) * YS_PITCH + col] + bv,
                        ys[(2 * r2 + 1) * YS_PITCH + col] + bv);
                    *(__nv_bfloat162*)&g_vt[(size_t)gn * MM + 2 * r2] = pv;
                }
            }
        }
        __syncthreads();
    }
}

// ---------------------------------------------------------------------------
extern "C" void kernel_launch(void* const* d_in, const int* in_sizes, int n_in,
                              void* d_out, int out_size) {
    const float* x     = (const float*)d_in[0];
    const float* gamma = (const float*)d_in[1];
    const float* beta  = (const float*)d_in[2];
    const float* W1    = (const float*)d_in[3];
    const float* b1    = (const float*)d_in[4];
    const float* W2    = (const float*)d_in[5];
    const float* b2    = (const float*)d_in[6];
    const float* Wslm  = (const float*)d_in[7];
    const float* bslm  = (const float*)d_in[8];
    const float* slw   = (const float*)d_in[9];
    const int*   slidx = (const int*)d_in[10];
    float* out = (float*)d_out;

    cudaFuncSetAttribute(gemm_kernel<VVN, false>,
                         cudaFuncAttributeMaxDynamicSharedMemorySize, SMEM_BYTES);
    cudaFuncSetAttribute(gemm_kernel<SSN, true>,
                         cudaFuncAttributeMaxDynamicSharedMemorySize, SMEM_BYTES);

    bn_stats_kernel<<<LL, 256>>>(x, gamma, beta);
    h_kernel<<<MM, 512>>>(x, W1, b1);
    gemm_kernel<VVN, false><<<(VVN + 127) / 128, 256, SMEM_BYTES>>>(
        Wslm, bslm, nullptr, nullptr, nullptr);
    gemm_kernel<SSN, true><<<(SSN + 127) / 128, 256, SMEM_BYTES>>>(
        W2, b2, slw, slidx, out);
}

// round 7
// speedup vs baseline: 5.0618x; 1.3759x over previous
#include <cuda_runtime.h>
#include <cuda_bf16.h>
#include <cuda_fp16.h>

#define BB 2
#define LL 64
#define DD 1024
#define HH 512
#define SSN 50000
#define VVN 40000
#define KK 32
#define MM 128
#define BKC 32
#define NTV 313     // ceil(40000/128)
#define NTY 391     // ceil(50000/128)

// ---------------- device scratch ----------------
__device__ float g_scale[LL];
__device__ float g_shift[LL];
__device__ __align__(16) __half g_hhi[MM * HH];                 // h hi [m][k] fp16
__device__ __align__(16) __half g_hlo[MM * HH];                 // h lo [m][k] fp16
__device__ __align__(16) __nv_bfloat16 g_vt[(size_t)VVN * MM];  // v^T bf16 [V][128]

// ---------------- smem layout (bytes) ----------------
#define A_HI_OFF 0          // [128][32] fp16, 64B rows, XOR swizzle (8192)
#define A_LO_OFF 8192
#define B_OFF    16384      // [32][136] fp16, 272B rows (8704)
#define STAGE_SZ 25088      // x2 stages = 50176
#define YS_PITCH 66         // ys[128][66] f32 = 33792 (overlays stage 0)
#define BIA_OFF  33792      // b_s[64]
#define SMEM_BYTES 50176

__device__ __forceinline__ unsigned smem_u32(const void* p) {
    unsigned a;
    asm("{ .reg .u64 t; cvta.to.shared.u64 t, %1; cvt.u32.u64 %0, t; }"
        : "=r"(a) : "l"(p));
    return a;
}
#define CP_ASYNC16(dst, src) \
    asm volatile("cp.async.cg.shared.global [%0], [%1], 16;" :: "r"(dst), "l"(src))
#define CP_COMMIT() asm volatile("cp.async.commit_group;" ::: "memory")
#define CP_WAIT0()  asm volatile("cp.async.wait_group 0;" ::: "memory")

__device__ __forceinline__ void ldsm4(unsigned& r0, unsigned& r1, unsigned& r2,
                                      unsigned& r3, unsigned addr) {
    asm volatile("ldmatrix.sync.aligned.m8n8.x4.shared.b16 {%0,%1,%2,%3}, [%4];"
                 : "=r"(r0), "=r"(r1), "=r"(r2), "=r"(r3) : "r"(addr));
}
__device__ __forceinline__ void ldsm4t(unsigned& r0, unsigned& r1, unsigned& r2,
                                       unsigned& r3, unsigned addr) {
    asm volatile("ldmatrix.sync.aligned.m8n8.x4.trans.shared.b16 {%0,%1,%2,%3}, [%4];"
                 : "=r"(r0), "=r"(r1), "=r"(r2), "=r"(r3) : "r"(addr));
}
__device__ __forceinline__ void mma_f16(float* d, const unsigned* a,
                                        unsigned b0, unsigned b1) {
    asm volatile(
        "mma.sync.aligned.m16n8k16.row.col.f32.f16.f16.f32 "
        "{%0,%1,%2,%3}, {%4,%5,%6,%7}, {%8,%9}, {%0,%1,%2,%3};"
        : "+f"(d[0]), "+f"(d[1]), "+f"(d[2]), "+f"(d[3])
        : "r"(a[0]), "r"(a[1]), "r"(a[2]), "r"(a[3]), "r"(b0), "r"(b1));
}

// ---------------------------------------------------------------------------
// Kernel 1: BN stats
// ---------------------------------------------------------------------------
__global__ void bn_stats_kernel(const float* __restrict__ x,
                                const float* __restrict__ gamma,
                                const float* __restrict__ beta) {
    int l = blockIdx.x, t = threadIdx.x;
    float s = 0.f, s2 = 0.f;
    for (int i = t; i < BB * DD; i += 256) {
        int b = i >> 10, d = i & (DD - 1);
        float v = x[(b * LL + l) * DD + d];
        s += v; s2 += v * v;
    }
    __shared__ float rs[256], rs2[256];
    rs[t] = s; rs2[t] = s2;
    __syncthreads();
    for (int o = 128; o > 0; o >>= 1) {
        if (t < o) { rs[t] += rs[t + o]; rs2[t] += rs2[t + o]; }
        __syncthreads();
    }
    if (t == 0) {
        const float inv_n = 1.f / (BB * DD);
        float mean = rs[0] * inv_n;
        float var  = rs2[0] * inv_n - mean * mean;
        float sc = gamma[l] * rsqrtf(var + 1e-5f);
        g_scale[l] = sc;
        g_shift[l] = beta[l] - mean * sc;
    }
}

// ---------------------------------------------------------------------------
// Kernel 2: h = relu(xn@W1+b1) -> fp16 hi/lo [m][k]; one bl-row per block
// ---------------------------------------------------------------------------
__global__ __launch_bounds__(512) void h_kernel(const float* __restrict__ x,
                                                const float* __restrict__ W1,
                                                const float* __restrict__ b1) {
    __shared__ float xs[DD];
    int t = threadIdx.x;
    int bl = blockIdx.x, l = bl & (LL - 1);
    for (int d = t; d < DD; d += 512)
        xs[d] = x[bl * DD + d] * g_scale[l] + g_shift[l];
    __syncthreads();
    float acc = 0.f;
#pragma unroll 16
    for (int d = 0; d < DD; ++d) acc += xs[d] * W1[d * HH + t];
    float v = fmaxf(acc + b1[t], 0.f);
    __half hi = __float2half_rn(v);
    g_hhi[bl * HH + t] = hi;
    g_hlo[bl * HH + t] = __float2half_rn(v - __half2float(hi));
}

// ---------------------------------------------------------------------------
// HMMA GEMM: both matrices in one grid. v-tiles (bid<NTV) write g_vt bf16;
// y-tiles write out fp32 directly. fp16 2-pass split: (A_hi + A_lo) @ B_fp16.
// ---------------------------------------------------------------------------
__global__ __launch_bounds__(256, 2) void gemm_kernel(const float* __restrict__ Wv,
                                                      const float* __restrict__ bv,
                                                      const float* __restrict__ Wy,
                                                      const float* __restrict__ by,
                                                      float* __restrict__ out) {
    extern __shared__ __align__(128) char smem[];
    const int t = threadIdx.x;
    const int lane = t & 31, w = t >> 5;
    const int wm = (w >> 2) * 64, wn = (w & 3) * 32;
    const bool isY = blockIdx.x >= NTV;
    const float* __restrict__ W    = isY ? Wy : Wv;
    const float* __restrict__ bias = isY ? by : bv;
    const int NN  = isY ? SSN : VVN;
    const int n0g = (isY ? blockIdx.x - NTV : blockIdx.x) * 128;
    const unsigned sb = smem_u32(smem);

    const int bk = t >> 3;              // B row (k)
    const int bn = (t & 7) * 16;        // B col base

    float acc[4][4][4];
#pragma unroll
    for (int i = 0; i < 4; ++i)
#pragma unroll
        for (int j = 0; j < 4; ++j)
#pragma unroll
            for (int e = 0; e < 4; ++e) acc[i][j][e] = 0.f;

    uint2 pBc[4];

    auto copyA = [&](int c) {
        unsigned stg = sb + (unsigned)(c & 1) * STAGE_SZ;
        int k0 = c * BKC;
#pragma unroll
        for (int j = 0; j < 2; ++j) {
            int id = t + 256 * j;
            int m = id >> 2, ch = id & 3;
            unsigned off = (unsigned)(m * 64 + ((ch ^ ((m >> 1) & 3))) * 16);
            CP_ASYNC16(stg + A_HI_OFF + off, &g_hhi[m * HH + k0 + ch * 8]);
            CP_ASYNC16(stg + A_LO_OFF + off, &g_hlo[m * HH + k0 + ch * 8]);
        }
    };
    auto prefB = [&](int c) {
        int k0 = c * BKC;
        const float* wr = W + (size_t)(k0 + bk) * NN + n0g + bn;
#pragma unroll
        for (int j = 0; j < 4; ++j) {
            int gn = n0g + bn + j * 4;
            float4 v = (gn < NN) ? *(const float4*)(wr + j * 4)
                                 : make_float4(0.f, 0.f, 0.f, 0.f);
            __half2 h0 = __floats2half2_rn(v.x, v.y);
            __half2 h1 = __floats2half2_rn(v.z, v.w);
            pBc[j].x = *(unsigned*)&h0;
            pBc[j].y = *(unsigned*)&h1;
        }
    };
    auto stsB = [&](int c) {
        char* st = smem + (c & 1) * STAGE_SZ;
#pragma unroll
        for (int j = 0; j < 4; ++j)
            *(uint2*)(st + B_OFF + bk * 272 + (bn + j * 4) * 2) = pBc[j];
    };

    copyA(0); CP_COMMIT();
    prefB(0); stsB(0);
    CP_WAIT0();
    __syncthreads();

    const unsigned bBase = (unsigned)((lane & 15) * 272 +
                                      (wn + (lane >> 4) * 8) * 2);

    for (int c = 0; c < HH / BKC; ++c) {
        if (c < HH / BKC - 1) {
            prefB(c + 1);
            copyA(c + 1); CP_COMMIT();
        }
        const unsigned stgb = sb + (unsigned)(c & 1) * STAGE_SZ;
#pragma unroll
        for (int ks = 0; ks < 2; ++ks) {
            unsigned ah[4][4], al[4][4], bf[2][4];
#pragma unroll
            for (int mi = 0; mi < 4; ++mi) {
                int row = wm + mi * 16 + (lane & 15);
                int chunk = (ks * 2 + (lane >> 4)) ^ ((row >> 1) & 3);
                ldsm4(ah[mi][0], ah[mi][1], ah[mi][2], ah[mi][3],
                      stgb + A_HI_OFF + row * 64 + chunk * 16);
            }
#pragma unroll
            for (int g = 0; g < 2; ++g)
                ldsm4t(bf[g][0], bf[g][1], bf[g][2], bf[g][3],
                       stgb + B_OFF + bBase + ks * 4352 + g * 32);
#pragma unroll
            for (int mi = 0; mi < 4; ++mi)
#pragma unroll
                for (int nj = 0; nj < 4; ++nj)
                    mma_f16(acc[mi][nj], ah[mi],
                            bf[nj >> 1][(nj & 1) * 2],
                            bf[nj >> 1][(nj & 1) * 2 + 1]);
#pragma unroll
            for (int mi = 0; mi < 4; ++mi) {
                int row = wm + mi * 16 + (lane & 15);
                int chunk = (ks * 2 + (lane >> 4)) ^ ((row >> 1) & 3);
                ldsm4(al[mi][0], al[mi][1], al[mi][2], al[mi][3],
                      stgb + A_LO_OFF + row * 64 + chunk * 16);
            }
#pragma unroll
            for (int mi = 0; mi < 4; ++mi)
#pragma unroll
                for (int nj = 0; nj < 4; ++nj)
                    mma_f16(acc[mi][nj], al[mi],
                            bf[nj >> 1][(nj & 1) * 2],
                            bf[nj >> 1][(nj & 1) * 2 + 1]);
        }
        if (c < HH / BKC - 1) {
            stsB(c + 1);
            CP_WAIT0();
            __syncthreads();
        }
    }
    __syncthreads();

    if (isY) {
        // direct stores: each lane owns (row, 2 consecutive cols) pairs
#pragma unroll
        for (int mi = 0; mi < 4; ++mi)
#pragma unroll
            for (int nj = 0; nj < 4; ++nj) {
                int r0 = wm + mi * 16 + (lane >> 2);
                int col = wn + nj * 8 + (lane & 3) * 2;
                int gn = n0g + col;
                float* d = acc[mi][nj];
                if (gn < SSN) {
                    float b0 = __ldg(&bias[gn]);
                    out[(size_t)r0 * SSN + gn]       = d[0] + b0;
                    out[(size_t)(r0 + 8) * SSN + gn] = d[2] + b0;
                }
                if (gn + 1 < SSN) {
                    float b1 = __ldg(&bias[gn + 1]);
                    out[(size_t)r0 * SSN + gn + 1]       = d[1] + b1;
                    out[(size_t)(r0 + 8) * SSN + gn + 1] = d[3] + b1;
                }
            }
    } else {
        // transpose through smem -> g_vt bf16 [n][m]
        float* ys  = (float*)smem;
        float* b_s = (float*)(smem + BIA_OFF);
#pragma unroll 1
        for (int hf = 0; hf < 2; ++hf) {
            const int h0 = hf * 64;
            if (t < 64) {
                int gn = n0g + h0 + t;
                b_s[t] = (gn < VVN) ? bias[gn] : 0.f;
            }
            if (((w & 3) >> 1) == hf) {
                int wn2 = ((w & 3) & 1) * 32;
#pragma unroll
                for (int mi = 0; mi < 4; ++mi)
#pragma unroll
                    for (int nj = 0; nj < 4; ++nj) {
                        int row = wm + mi * 16 + (lane >> 2);
                        int col = wn2 + nj * 8 + (lane & 3) * 2;
                        float* d = acc[mi][nj];
                        ys[row * YS_PITCH + col]           = d[0];
                        ys[row * YS_PITCH + col + 1]       = d[1];
                        ys[(row + 8) * YS_PITCH + col]     = d[2];
                        ys[(row + 8) * YS_PITCH + col + 1] = d[3];
                    }
            }
            __syncthreads();
            for (int i = t; i < 64 * 64; i += 256) {
                int r2 = i & 63, col = i >> 6;
                int gn = n0g + h0 + col;
                if (gn < VVN) {
                    float bvv = b_s[col];
                    __nv_bfloat162 pv = __floats2bfloat162_rn(
                        ys[(2 * r2) * YS_PITCH + col] + bvv,
                        ys[(2 * r2 + 1) * YS_PITCH + col] + bvv);
                    *(__nv_bfloat162*)&g_vt[(size_t)gn * MM + 2 * r2] = pv;
                }
            }
            __syncthreads();
        }
    }
}

// ---------------------------------------------------------------------------
// Gather kernel: out[m, s] += 0.1 * sum_k w[s,k] * vt[idx[s,k]][m]
// block = 32 s-columns; warp = 4 columns; lane covers 4 m rows (8B of vt row)
// ---------------------------------------------------------------------------
__global__ __launch_bounds__(256) void gather_kernel(const float* __restrict__ slw,
                                                     const int* __restrict__ slidx,
                                                     float* __restrict__ out) {
    __shared__ float sacc[32][132];
    __shared__ int   idx_s[1024];
    __shared__ float w_s[1024];
    const int t = threadIdx.x, lane = t & 31, w = t >> 5;
    const int s0 = blockIdx.x * 32;

    for (int i = t; i < 1024; i += 256) {
        int gs = s0 + (i >> 5);
        idx_s[i] = (gs < SSN) ? slidx[(size_t)gs * KK + (i & 31)] : 0;
        w_s[i]   = (gs < SSN) ? slw[(size_t)gs * KK + (i & 31)] : 0.f;
    }
    __syncthreads();

    float acc[4][4];
#pragma unroll
    for (int c = 0; c < 4; ++c)
#pragma unroll
        for (int j = 0; j < 4; ++j) acc[c][j] = 0.f;

    const int mb = lane * 4;
#pragma unroll 4
    for (int k = 0; k < KK; ++k) {
#pragma unroll
        for (int cj = 0; cj < 4; ++cj) {
            int ci = w * 4 + cj;
            int ip = idx_s[ci * KK + k];
            float wk = w_s[ci * KK + k];
            uint2 raw = *(const uint2*)&g_vt[(size_t)ip * MM + mb];
            __nv_bfloat162 p0 = *(__nv_bfloat162*)&raw.x;
            __nv_bfloat162 p1 = *(__nv_bfloat162*)&raw.y;
            float2 f0 = __bfloat1622float2(p0);
            float2 f1 = __bfloat1622float2(p1);
            acc[cj][0] += wk * f0.x;
            acc[cj][1] += wk * f0.y;
            acc[cj][2] += wk * f1.x;
            acc[cj][3] += wk * f1.y;
        }
    }
#pragma unroll
    for (int cj = 0; cj < 4; ++cj)
        *(float4*)&sacc[w * 4 + cj][mb] =
            make_float4(acc[cj][0], acc[cj][1], acc[cj][2], acc[cj][3]);
    __syncthreads();

    for (int i = t; i < 32 * MM; i += 256) {
        int m = i >> 5, col = i & 31;
        int gs = s0 + col;
        if (gs < SSN)
            out[(size_t)m * SSN + gs] += 0.1f * sacc[col][m];
    }
}

// ---------------------------------------------------------------------------
extern "C" void kernel_launch(void* const* d_in, const int* in_sizes, int n_in,
                              void* d_out, int out_size) {
    const float* x     = (const float*)d_in[0];
    const float* gamma = (const float*)d_in[1];
    const float* beta  = (const float*)d_in[2];
    const float* W1    = (const float*)d_in[3];
    const float* b1    = (const float*)d_in[4];
    const float* W2    = (const float*)d_in[5];
    const float* b2    = (const float*)d_in[6];
    const float* Wslm  = (const float*)d_in[7];
    const float* bslm  = (const float*)d_in[8];
    const float* slw   = (const float*)d_in[9];
    const int*   slidx = (const int*)d_in[10];
    float* out = (float*)d_out;

    cudaFuncSetAttribute(gemm_kernel,
                         cudaFuncAttributeMaxDynamicSharedMemorySize, SMEM_BYTES);

    bn_stats_kernel<<<LL, 256>>>(x, gamma, beta);
    h_kernel<<<MM, 512>>>(x, W1, b1);
    gemm_kernel<<<NTV + NTY, 256, SMEM_BYTES>>>(Wslm, bslm, W2, b2, out);
    gather_kernel<<<(SSN + 31) / 32, 256>>>(slw, slidx, out);
}